// round 5
// baseline (speedup 1.0000x reference)
#include <cuda_runtime.h>
#include <cstddef>

// Problem dims (fixed by the reference)
#define NN     20000
#define EE     320000
#define INC    2000
#define HIDDEN 512
#define OUTD   256
#define QD     100

// ---------------------------------------------------------------------------
// Scratch (device globals; no dynamic allocation allowed)
// ---------------------------------------------------------------------------
__device__ float g_h [NN * HIDDEN];   // pre-aggregation features (reused, 512 & 256 wide)
__device__ float g_xs[NN * HIDDEN];   // relu(gcn(x_RNA, sim))
__device__ float g_xd[NN * HIDDEN];   // relu(gcn(x_RNA, dist))
__device__ float g_dinv[3 * NN];      // deg^-0.5 for sim / dist / common

// ---------------------------------------------------------------------------
// Small utility kernels
// ---------------------------------------------------------------------------
__global__ void fill_ones(float* __restrict__ p, int n) {
    int i = blockIdx.x * blockDim.x + threadIdx.x;
    if (i < n) p[i] = 1.0f;
}

__global__ void deg_accum(const int* __restrict__ dst, const float* __restrict__ w,
                          float* __restrict__ deg, int E) {
    int e = blockIdx.x * blockDim.x + threadIdx.x;
    if (e < E) atomicAdd(&deg[dst[e]], w[e]);
}

__global__ void rsqrt_inplace(float* __restrict__ p, int n) {
    int i = blockIdx.x * blockDim.x + threadIdx.x;
    if (i < n) p[i] = rsqrtf(p[i]);   // deg >= 1 always (self-loop weight 1)
}

__global__ void relu_inplace(float* __restrict__ p, int n) {
    int i = blockIdx.x * blockDim.x + threadIdx.x;
    if (i < n) p[i] = fmaxf(p[i], 0.0f);
}

// agg[i,f] = h[i,f] * dinv[i]^2 + bias[f]   (self-loop term + bias, overwrites dst)
__global__ void agg_init(const float* __restrict__ h, const float* __restrict__ dinv,
                         const float* __restrict__ bias, float* __restrict__ agg, int F) {
    int idx4 = blockIdx.x * blockDim.x + threadIdx.x;
    int fdiv4 = F >> 2;
    int total4 = NN * fdiv4;
    if (idx4 >= total4) return;
    int node = idx4 / fdiv4;
    int f4   = idx4 - node * fdiv4;
    float di = dinv[node];
    float s  = di * di;
    float4 hv = reinterpret_cast<const float4*>(h)[idx4];
    float4 bv = *reinterpret_cast<const float4*>(bias + (f4 << 2));
    float4 o;
    o.x = hv.x * s + bv.x;
    o.y = hv.y * s + bv.y;
    o.z = hv.z * s + bv.z;
    o.w = hv.w * s + bv.w;
    reinterpret_cast<float4*>(agg)[idx4] = o;
}

// Scatter-add: agg[dst] += h[src] * (dinv[src]*w*dinv[dst]) using vector reductions.
// blockDim must be a multiple of F/4. Each sub-group of F/4 threads handles one edge.
__global__ void edge_agg(const float* __restrict__ h, float* __restrict__ agg,
                         const int* __restrict__ src, const int* __restrict__ dst,
                         const float* __restrict__ ew, const float* __restrict__ dinv,
                         int E, int F) {
    int lanes = F >> 2;                       // float4 lanes per edge (128 or 64)
    int epb   = blockDim.x / lanes;           // edges per block
    int le    = threadIdx.x / lanes;
    int lane  = threadIdx.x - le * lanes;
    int e     = blockIdx.x * epb + le;
    if (e >= E) return;

    int s = src[e];
    int d = dst[e];
    float norm = dinv[s] * ew[e] * dinv[d];

    float4 hv = *reinterpret_cast<const float4*>(h + (size_t)s * F + (lane << 2));
    float* outp = agg + (size_t)d * F + (lane << 2);
    // Vectorized fp32 reduction (sm_90+): 1 L2 atomic op per 16 bytes.
    asm volatile("red.global.add.v4.f32 [%0], {%1, %2, %3, %4};"
                 :: "l"(outp),
                    "f"(hv.x * norm), "f"(hv.y * norm),
                    "f"(hv.z * norm), "f"(hv.w * norm)
                 : "memory");
}

// ---------------------------------------------------------------------------
// Tiled fp32 GEMM: C[M,N] (=|+=) A[M,K] @ B[K,N] (+ bias)
// BM=BN=128, BK=8, TM=TN=8, 256 threads.
// ---------------------------------------------------------------------------
template <bool ACCUM, bool ADD_BIAS>
__global__ __launch_bounds__(256)
void sgemm_kernel(const float* __restrict__ A, const float* __restrict__ B,
                  const float* __restrict__ bias, float* __restrict__ C,
                  int M, int N, int K) {
    constexpr int BM = 128, BN = 128, BK = 8, TM = 8, TN = 8;
    __shared__ float As[BK][BM];
    __shared__ float Bs[BK][BN];

    int tid = threadIdx.x;
    int block_row = blockIdx.y * BM;
    int block_col = blockIdx.x * BN;

    int tx = tid % (BN / TN);   // 0..15
    int ty = tid / (BN / TN);   // 0..15

    float acc[TM][TN];
    #pragma unroll
    for (int i = 0; i < TM; i++)
        #pragma unroll
        for (int j = 0; j < TN; j++) acc[i][j] = 0.0f;

    // A tile load mapping: 128x8 floats, float4 along K (BK/4 = 2 quads per row)
    int a_row = tid >> 1;            // 0..127
    int a_col = (tid & 1) << 2;      // 0 or 4
    // B tile load mapping: 8x128 floats, float4 along N
    int b_row = tid >> 5;            // 0..7
    int b_col = (tid & 31) << 2;     // 0..124

    for (int k0 = 0; k0 < K; k0 += BK) {
        // --- load A tile (transposed into As[k][m]) ---
        {
            int gm = block_row + a_row;
            int gk = k0 + a_col;
            float4 v = make_float4(0.f, 0.f, 0.f, 0.f);
            if (gm < M) {
                if (gk + 3 < K) {
                    v = *reinterpret_cast<const float4*>(A + (size_t)gm * K + gk);
                } else {
                    float t[4] = {0.f, 0.f, 0.f, 0.f};
                    #pragma unroll
                    for (int i = 0; i < 4; i++)
                        if (gk + i < K) t[i] = A[(size_t)gm * K + gk + i];
                    v = make_float4(t[0], t[1], t[2], t[3]);
                }
            }
            As[a_col + 0][a_row] = v.x;
            As[a_col + 1][a_row] = v.y;
            As[a_col + 2][a_row] = v.z;
            As[a_col + 3][a_row] = v.w;
        }
        // --- load B tile ---
        {
            int gk = k0 + b_row;
            int gn = block_col + b_col;
            float4 v = make_float4(0.f, 0.f, 0.f, 0.f);
            if (gk < K) {
                if (gn + 3 < N) {
                    v = *reinterpret_cast<const float4*>(B + (size_t)gk * N + gn);
                } else {
                    float t[4] = {0.f, 0.f, 0.f, 0.f};
                    #pragma unroll
                    for (int i = 0; i < 4; i++)
                        if (gn + i < N) t[i] = B[(size_t)gk * N + gn + i];
                    v = make_float4(t[0], t[1], t[2], t[3]);
                }
            }
            *reinterpret_cast<float4*>(&Bs[b_row][b_col]) = v;
        }
        __syncthreads();

        #pragma unroll
        for (int kk = 0; kk < BK; kk++) {
            float a_frag[TM], b_frag[TN];
            float4 a0 = *reinterpret_cast<const float4*>(&As[kk][ty * TM]);
            float4 a1 = *reinterpret_cast<const float4*>(&As[kk][ty * TM + 4]);
            a_frag[0] = a0.x; a_frag[1] = a0.y; a_frag[2] = a0.z; a_frag[3] = a0.w;
            a_frag[4] = a1.x; a_frag[5] = a1.y; a_frag[6] = a1.z; a_frag[7] = a1.w;
            float4 b0 = *reinterpret_cast<const float4*>(&Bs[kk][tx * TN]);
            float4 b1 = *reinterpret_cast<const float4*>(&Bs[kk][tx * TN + 4]);
            b_frag[0] = b0.x; b_frag[1] = b0.y; b_frag[2] = b0.z; b_frag[3] = b0.w;
            b_frag[4] = b1.x; b_frag[5] = b1.y; b_frag[6] = b1.z; b_frag[7] = b1.w;
            #pragma unroll
            for (int i = 0; i < TM; i++)
                #pragma unroll
                for (int j = 0; j < TN; j++)
                    acc[i][j] += a_frag[i] * b_frag[j];
        }
        __syncthreads();
    }

    // --- epilogue ---
    #pragma unroll
    for (int i = 0; i < TM; i++) {
        int gm = block_row + ty * TM + i;
        if (gm >= M) continue;
        #pragma unroll
        for (int j = 0; j < TN; j += 4) {
            int gn = block_col + tx * TN + j;
            if (gn + 3 < N) {
                float4 v = make_float4(acc[i][j], acc[i][j + 1], acc[i][j + 2], acc[i][j + 3]);
                if (ADD_BIAS) {
                    v.x += bias[gn]; v.y += bias[gn + 1];
                    v.z += bias[gn + 2]; v.w += bias[gn + 3];
                }
                if (ACCUM) {
                    float4 old = *reinterpret_cast<const float4*>(C + (size_t)gm * N + gn);
                    v.x += old.x; v.y += old.y; v.z += old.z; v.w += old.w;
                }
                *reinterpret_cast<float4*>(C + (size_t)gm * N + gn) = v;
            } else {
                for (int q = 0; q < 4; q++) {
                    int g = gn + q;
                    if (g >= N) break;
                    float v = acc[i][j + q];
                    if (ADD_BIAS) v += bias[g];
                    if (ACCUM) v += C[(size_t)gm * N + g];
                    C[(size_t)gm * N + g] = v;
                }
            }
        }
    }
}

template <bool ACCUM, bool ADD_BIAS>
static void gemm(const float* A, const float* B, const float* bias, float* C,
                 int M, int N, int K) {
    dim3 grid((N + 127) / 128, (M + 127) / 128);
    sgemm_kernel<ACCUM, ADD_BIAS><<<grid, 256>>>(A, B, bias, C, M, N, K);
}

// ---------------------------------------------------------------------------
// Launch orchestration
// ---------------------------------------------------------------------------
extern "C" void kernel_launch(void* const* d_in, const int* in_sizes, int n_in,
                              void* d_out, int out_size) {
    const float* x_RNA     = (const float*)d_in[0];
    const float* x_ADT     = (const float*)d_in[1];
    const int*   sim_ei    = (const int*)  d_in[2];   // [2,E]: row0=src, row1=dst
    const float* sim_ew    = (const float*)d_in[3];
    const int*   dist_ei   = (const int*)  d_in[4];
    const float* dist_ew   = (const float*)d_in[5];
    const int*   common_ei = (const int*)  d_in[6];
    const float* common_ew = (const float*)d_in[7];
    const float* W_rna1    = (const float*)d_in[8];
    const float* b_rna1    = (const float*)d_in[9];
    const float* W_rna2    = (const float*)d_in[10];
    const float* b_rna2    = (const float*)d_in[11];
    const float* W_p3      = (const float*)d_in[12];
    const float* b_p3      = (const float*)d_in[13];
    const float* W_sim     = (const float*)d_in[14];
    const float* b_sim     = (const float*)d_in[15];
    const float* W_dist    = (const float*)d_in[16];
    const float* b_dist    = (const float*)d_in[17];
    const float* W_f1      = (const float*)d_in[18];
    const float* b_f1      = (const float*)d_in[19];
    const float* W_f2      = (const float*)d_in[20];
    const float* b_f2      = (const float*)d_in[21];

    float* out = (float*)d_out;
    const size_t SEC = (size_t)NN * OUTD;     // 5,120,000 elements per output tensor
    float* out_xsim  = out;
    float* out_xdist = out + SEC;
    float* out_fused = out + 2 * SEC;
    float* out_fprо  = out + 3 * SEC;
    float* out_pro   = out + 4 * SEC;

    float *h, *xs, *xd, *dinv;
    cudaGetSymbolAddress((void**)&h,    g_h);
    cudaGetSymbolAddress((void**)&xs,   g_xs);
    cudaGetSymbolAddress((void**)&xd,   g_xd);
    cudaGetSymbolAddress((void**)&dinv, g_dinv);
    float* dinv_sim    = dinv;
    float* dinv_dist   = dinv + NN;
    float* dinv_common = dinv + 2 * NN;

    // ---- degree normalization for all three graphs ----
    fill_ones<<<(3 * NN + 255) / 256, 256>>>(dinv, 3 * NN);               // self-loop weight 1
    deg_accum<<<(EE + 255) / 256, 256>>>(sim_ei + EE,    sim_ew,    dinv_sim,    EE);
    deg_accum<<<(EE + 255) / 256, 256>>>(dist_ei + EE,   dist_ew,   dinv_dist,   EE);
    deg_accum<<<(EE + 255) / 256, 256>>>(common_ei + EE, common_ew, dinv_common, EE);
    rsqrt_inplace<<<(3 * NN + 255) / 256, 256>>>(dinv, 3 * NN);

    const int grid512 = (NN * (HIDDEN / 4) + 255) / 256;
    const int grid256 = (NN * (OUTD / 4) + 255) / 256;
    const int egrid512 = (EE + 1) / 2;   // 2 edges/block @ F=512, 256 threads
    const int egrid256 = (EE + 3) / 4;   // 4 edges/block @ F=256

    // ---- Layer 1, sim branch: xs = relu(gcn(x_RNA, sim; W_rna1, b_rna1)) ----
    gemm<false, false>(x_RNA, W_rna1, nullptr, h, NN, HIDDEN, INC);
    agg_init<<<grid512, 256>>>(h, dinv_sim, b_rna1, xs, HIDDEN);
    edge_agg<<<egrid512, 256>>>(h, xs, sim_ei, sim_ei + EE, sim_ew, dinv_sim, EE, HIDDEN);
    relu_inplace<<<(NN * HIDDEN + 255) / 256, 256>>>(xs, NN * HIDDEN);

    // ---- Layer 1, dist branch: xd = relu(gcn(x_RNA, dist; W_rna2, b_rna2)) ----
    gemm<false, false>(x_RNA, W_rna2, nullptr, h, NN, HIDDEN, INC);
    agg_init<<<grid512, 256>>>(h, dinv_dist, b_rna2, xd, HIDDEN);
    edge_agg<<<egrid512, 256>>>(h, xd, dist_ei, dist_ei + EE, dist_ew, dinv_dist, EE, HIDDEN);
    relu_inplace<<<(NN * HIDDEN + 255) / 256, 256>>>(xd, NN * HIDDEN);

    // ---- Layer 2: x_sim = gcn(xs, sim; W_sim, b_sim) -> d_out[0] ----
    gemm<false, false>(xs, W_sim, nullptr, h, NN, OUTD, HIDDEN);
    agg_init<<<grid256, 256>>>(h, dinv_sim, b_sim, out_xsim, OUTD);
    edge_agg<<<egrid256, 256>>>(h, out_xsim, sim_ei, sim_ei + EE, sim_ew, dinv_sim, EE, OUTD);

    // ---- Layer 2: x_dist = gcn(xd, dist; W_dist, b_dist) -> d_out[1] ----
    gemm<false, false>(xd, W_dist, nullptr, h, NN, OUTD, HIDDEN);
    agg_init<<<grid256, 256>>>(h, dinv_dist, b_dist, out_xdist, OUTD);
    edge_agg<<<egrid256, 256>>>(h, out_xdist, dist_ei, dist_ei + EE, dist_ew, dinv_dist, EE, OUTD);

    // ---- pro = gcn(x_ADT, common; W_p3, b_p3) -> d_out[4] ----
    gemm<false, false>(x_ADT, W_p3, nullptr, h, NN, OUTD, QD);
    agg_init<<<grid256, 256>>>(h, dinv_common, b_p3, out_pro, OUTD);
    edge_agg<<<egrid256, 256>>>(h, out_pro, common_ei, common_ei + EE, common_ew, dinv_common, EE, OUTD);

    // ---- fused = concat(x_sim, x_dist) @ W_f1 + b_f1  (K-split) -> d_out[2] ----
    gemm<false, true >(out_xsim,  W_f1,               b_f1,    out_fused, NN, OUTD, OUTD);
    gemm<true,  false>(out_xdist, W_f1 + OUTD * OUTD, nullptr, out_fused, NN, OUTD, OUTD);

    // ---- fused_pro = concat(fused, pro) @ W_f2 + b_f2 -> d_out[3] ----
    gemm<false, true >(out_fused, W_f2,               b_f2,    out_fprо, NN, OUTD, OUTD);
    gemm<true,  false>(out_pro,   W_f2 + OUTD * OUTD, nullptr, out_fprо, NN, OUTD, OUTD);
}

// round 6
// speedup vs baseline: 2.9484x; 2.9484x over previous
#include <cuda_runtime.h>
#include <cstdint>
#include <cstddef>

// Problem dims (fixed by the reference)
#define NN     20000
#define EE     320000
#define INC    2000
#define HIDDEN 512
#define OUTD   256
#define QD     100

// ---------------------------------------------------------------------------
// Scratch (device globals; no dynamic allocation allowed)
// ---------------------------------------------------------------------------
__device__ float g_h [NN * HIDDEN];   // pre-aggregation features (reused, 512 & 256 wide)
__device__ float g_xs[NN * HIDDEN];   // relu(gcn(x_RNA, sim))
__device__ float g_xd[NN * HIDDEN];   // relu(gcn(x_RNA, dist))
__device__ float g_dinv[3 * NN];      // deg^-0.5 for sim / dist / common

// ---------------------------------------------------------------------------
// Small utility kernels
// ---------------------------------------------------------------------------
__global__ void fill_ones(float* __restrict__ p, int n) {
    int i = blockIdx.x * blockDim.x + threadIdx.x;
    if (i < n) p[i] = 1.0f;
}

__global__ void deg_accum(const int* __restrict__ dst, const float* __restrict__ w,
                          float* __restrict__ deg, int E) {
    int e = blockIdx.x * blockDim.x + threadIdx.x;
    if (e < E) atomicAdd(&deg[dst[e]], w[e]);
}

__global__ void rsqrt_inplace(float* __restrict__ p, int n) {
    int i = blockIdx.x * blockDim.x + threadIdx.x;
    if (i < n) p[i] = rsqrtf(p[i]);   // deg >= 1 always (self-loop weight 1)
}

__global__ void relu_inplace(float* __restrict__ p, int n) {
    int i = blockIdx.x * blockDim.x + threadIdx.x;
    if (i < n) p[i] = fmaxf(p[i], 0.0f);
}

// agg[i,f] = h[i,f] * dinv[i]^2 + bias[f]   (self-loop term + bias, overwrites dst)
__global__ void agg_init(const float* __restrict__ h, const float* __restrict__ dinv,
                         const float* __restrict__ bias, float* __restrict__ agg, int F) {
    int idx4 = blockIdx.x * blockDim.x + threadIdx.x;
    int fdiv4 = F >> 2;
    int total4 = NN * fdiv4;
    if (idx4 >= total4) return;
    int node = idx4 / fdiv4;
    int f4   = idx4 - node * fdiv4;
    float di = dinv[node];
    float s  = di * di;
    float4 hv = reinterpret_cast<const float4*>(h)[idx4];
    float4 bv = *reinterpret_cast<const float4*>(bias + (f4 << 2));
    float4 o;
    o.x = hv.x * s + bv.x;
    o.y = hv.y * s + bv.y;
    o.z = hv.z * s + bv.z;
    o.w = hv.w * s + bv.w;
    reinterpret_cast<float4*>(agg)[idx4] = o;
}

// Scatter-add: agg[dst] += h[src] * (dinv[src]*w*dinv[dst]) using vector reductions.
__global__ void edge_agg(const float* __restrict__ h, float* __restrict__ agg,
                         const int* __restrict__ src, const int* __restrict__ dst,
                         const float* __restrict__ ew, const float* __restrict__ dinv,
                         int E, int F) {
    int lanes = F >> 2;                       // float4 lanes per edge (128 or 64)
    int epb   = blockDim.x / lanes;           // edges per block
    int le    = threadIdx.x / lanes;
    int lane  = threadIdx.x - le * lanes;
    int e     = blockIdx.x * epb + le;
    if (e >= E) return;

    int s = src[e];
    int d = dst[e];
    float norm = dinv[s] * ew[e] * dinv[d];

    float4 hv = *reinterpret_cast<const float4*>(h + (size_t)s * F + (lane << 2));
    float* outp = agg + (size_t)d * F + (lane << 2);
    asm volatile("red.global.add.v4.f32 [%0], {%1, %2, %3, %4};"
                 :: "l"(outp),
                    "f"(hv.x * norm), "f"(hv.y * norm),
                    "f"(hv.z * norm), "f"(hv.w * norm)
                 : "memory");
}

// ---------------------------------------------------------------------------
// TF32 tensor-core GEMM: C[M,N] (=|+=) A[M,K] @ B[K,N] (+ bias)
// BM=128, BN=128, BK=16; 8 warps (2m x 4n), warp tile 64x32, mma m16n8k8.
// A smem [m][k] pitch 20 (ldmatrix conflict-free); B smem [k][n] pitch 136
// (scalar fragment LDS conflict-free: bank = 8k+n).
// Requirements used here: K % 4 == 0, N % 128 == 0 (true for all call sites).
// ---------------------------------------------------------------------------
__device__ __forceinline__ unsigned f2tf32(float x) {
    unsigned u;
    asm("cvt.rna.tf32.f32 %0, %1;" : "=r"(u) : "f"(x));
    return u;
}

template <bool ACCUM, bool ADD_BIAS>
__global__ void __launch_bounds__(256, 2)
tf32_gemm_kernel(const float* __restrict__ A, const float* __restrict__ B,
                 const float* __restrict__ bias, float* __restrict__ C,
                 int M, int N, int K) {
    constexpr int BM = 128, BN = 128, BK = 16;
    constexpr int AP = 20;    // A smem pitch (floats)
    constexpr int BP = 136;   // B smem pitch (floats)
    __shared__ float As[BM * AP];   // 10240 B
    __shared__ float Bs[BK * BP];   //  8704 B

    const int tid  = threadIdx.x;
    const int lane = tid & 31;
    const int warp = tid >> 5;
    const int wm   = warp >> 2;     // 0..1
    const int wn   = warp & 3;      // 0..3
    const int block_row = blockIdx.y * BM;
    const int block_col = blockIdx.x * BN;

    float acc[4][4][4];
    #pragma unroll
    for (int mt = 0; mt < 4; mt++)
        #pragma unroll
        for (int nt = 0; nt < 4; nt++)
            #pragma unroll
            for (int q = 0; q < 4; q++) acc[mt][nt][q] = 0.0f;

    // Global-load coordinates (each thread: 2 float4 of A, 2 float4 of B)
    const int ar = tid >> 2;              // A row within tile (+64*i)
    const int aq = (tid & 3) << 2;        // A k-offset within tile
    const int bk = tid >> 5;              // B k within tile (+8*i)
    const int bn = (tid & 31) << 2;       // B n-offset within tile

    // ldmatrix lane addresses for A fragments (per m-tile); ks adds 32 bytes
    const unsigned as_base = (unsigned)__cvta_generic_to_shared(As);
    const int r_in   = lane & 7;
    const int half_m = (lane >> 3) & 1;
    const int half_k = (lane >> 4) & 1;
    unsigned a_lm_addr[4];
    #pragma unroll
    for (int mt = 0; mt < 4; mt++) {
        int row = wm * 64 + mt * 16 + half_m * 8 + r_in;
        a_lm_addr[mt] = as_base + (unsigned)((row * AP + half_k * 4) * 4);
    }

    float4 pa[2], pb[2];

    auto fetch = [&](int k0) {
        #pragma unroll
        for (int i = 0; i < 2; i++) {
            int gm = block_row + ar + 64 * i;
            int gk = k0 + aq;
            pa[i] = (gm < M && gk < K)
                  ? *reinterpret_cast<const float4*>(A + (size_t)gm * K + gk)
                  : make_float4(0.f, 0.f, 0.f, 0.f);
            int gk2 = k0 + bk + 8 * i;
            pb[i] = (gk2 < K)
                  ? *reinterpret_cast<const float4*>(B + (size_t)gk2 * N + block_col + bn)
                  : make_float4(0.f, 0.f, 0.f, 0.f);
        }
    };
    auto stage = [&]() {
        #pragma unroll
        for (int i = 0; i < 2; i++) {
            float* pA = &As[(ar + 64 * i) * AP + aq];
            pA[0] = __uint_as_float(f2tf32(pa[i].x));
            pA[1] = __uint_as_float(f2tf32(pa[i].y));
            pA[2] = __uint_as_float(f2tf32(pa[i].z));
            pA[3] = __uint_as_float(f2tf32(pa[i].w));
            float* pB = &Bs[(bk + 8 * i) * BP + bn];
            pB[0] = __uint_as_float(f2tf32(pb[i].x));
            pB[1] = __uint_as_float(f2tf32(pb[i].y));
            pB[2] = __uint_as_float(f2tf32(pb[i].z));
            pB[3] = __uint_as_float(f2tf32(pb[i].w));
        }
    };

    fetch(0);
    stage();
    __syncthreads();

    for (int k0 = 0; k0 < K; k0 += BK) {
        const bool has_next = (k0 + BK) < K;
        if (has_next) fetch(k0 + BK);   // prefetch into registers

        #pragma unroll
        for (int ks = 0; ks < 2; ks++) {
            unsigned a[4][4];
            #pragma unroll
            for (int mt = 0; mt < 4; mt++) {
                asm volatile(
                    "ldmatrix.sync.aligned.m8n8.x4.shared.b16 {%0,%1,%2,%3}, [%4];"
                    : "=r"(a[mt][0]), "=r"(a[mt][1]), "=r"(a[mt][2]), "=r"(a[mt][3])
                    : "r"(a_lm_addr[mt] + (unsigned)(ks * 32)));
            }
            unsigned b[4][2];
            #pragma unroll
            for (int nt = 0; nt < 4; nt++) {
                int n = wn * 32 + nt * 8 + (lane >> 2);
                b[nt][0] = __float_as_uint(Bs[(ks * 8 +     (lane & 3)) * BP + n]);
                b[nt][1] = __float_as_uint(Bs[(ks * 8 + 4 + (lane & 3)) * BP + n]);
            }
            #pragma unroll
            for (int mt = 0; mt < 4; mt++)
                #pragma unroll
                for (int nt = 0; nt < 4; nt++) {
                    asm volatile(
                        "mma.sync.aligned.m16n8k8.row.col.f32.tf32.tf32.f32 "
                        "{%0,%1,%2,%3}, {%4,%5,%6,%7}, {%8,%9}, {%0,%1,%2,%3};"
                        : "+f"(acc[mt][nt][0]), "+f"(acc[mt][nt][1]),
                          "+f"(acc[mt][nt][2]), "+f"(acc[mt][nt][3])
                        : "r"(a[mt][0]), "r"(a[mt][1]), "r"(a[mt][2]), "r"(a[mt][3]),
                          "r"(b[nt][0]), "r"(b[nt][1]));
                }
        }

        if (has_next) {
            __syncthreads();
            stage();
        }
        __syncthreads();
    }

    // ---- epilogue ----
    #pragma unroll
    for (int mt = 0; mt < 4; mt++) {
        int r0 = block_row + wm * 64 + mt * 16 + (lane >> 2);
        #pragma unroll
        for (int nt = 0; nt < 4; nt++) {
            int c = block_col + wn * 32 + nt * 8 + 2 * (lane & 3);
            if (r0 < M) {
                float2 v = make_float2(acc[mt][nt][0], acc[mt][nt][1]);
                if (ADD_BIAS) { v.x += bias[c]; v.y += bias[c + 1]; }
                if (ACCUM) {
                    float2 o = *reinterpret_cast<const float2*>(C + (size_t)r0 * N + c);
                    v.x += o.x; v.y += o.y;
                }
                *reinterpret_cast<float2*>(C + (size_t)r0 * N + c) = v;
            }
            int r1 = r0 + 8;
            if (r1 < M) {
                float2 v = make_float2(acc[mt][nt][2], acc[mt][nt][3]);
                if (ADD_BIAS) { v.x += bias[c]; v.y += bias[c + 1]; }
                if (ACCUM) {
                    float2 o = *reinterpret_cast<const float2*>(C + (size_t)r1 * N + c);
                    v.x += o.x; v.y += o.y;
                }
                *reinterpret_cast<float2*>(C + (size_t)r1 * N + c) = v;
            }
        }
    }
}

template <bool ACCUM, bool ADD_BIAS>
static void gemm(const float* A, const float* B, const float* bias, float* C,
                 int M, int N, int K) {
    dim3 grid(N / 128, (M + 127) / 128);
    tf32_gemm_kernel<ACCUM, ADD_BIAS><<<grid, 256>>>(A, B, bias, C, M, N, K);
}

// ---------------------------------------------------------------------------
// Launch orchestration
// ---------------------------------------------------------------------------
extern "C" void kernel_launch(void* const* d_in, const int* in_sizes, int n_in,
                              void* d_out, int out_size) {
    const float* x_RNA     = (const float*)d_in[0];
    const float* x_ADT     = (const float*)d_in[1];
    const int*   sim_ei    = (const int*)  d_in[2];   // [2,E]: row0=src, row1=dst
    const float* sim_ew    = (const float*)d_in[3];
    const int*   dist_ei   = (const int*)  d_in[4];
    const float* dist_ew   = (const float*)d_in[5];
    const int*   common_ei = (const int*)  d_in[6];
    const float* common_ew = (const float*)d_in[7];
    const float* W_rna1    = (const float*)d_in[8];
    const float* b_rna1    = (const float*)d_in[9];
    const float* W_rna2    = (const float*)d_in[10];
    const float* b_rna2    = (const float*)d_in[11];
    const float* W_p3      = (const float*)d_in[12];
    const float* b_p3      = (const float*)d_in[13];
    const float* W_sim     = (const float*)d_in[14];
    const float* b_sim     = (const float*)d_in[15];
    const float* W_dist    = (const float*)d_in[16];
    const float* b_dist    = (const float*)d_in[17];
    const float* W_f1      = (const float*)d_in[18];
    const float* b_f1      = (const float*)d_in[19];
    const float* W_f2      = (const float*)d_in[20];
    const float* b_f2      = (const float*)d_in[21];

    float* out = (float*)d_out;
    const size_t SEC = (size_t)NN * OUTD;     // elements per output tensor
    float* out_xsim  = out;
    float* out_xdist = out + SEC;
    float* out_fused = out + 2 * SEC;
    float* out_fpro  = out + 3 * SEC;
    float* out_pro   = out + 4 * SEC;

    float *h, *xs, *xd, *dinv;
    cudaGetSymbolAddress((void**)&h,    g_h);
    cudaGetSymbolAddress((void**)&xs,   g_xs);
    cudaGetSymbolAddress((void**)&xd,   g_xd);
    cudaGetSymbolAddress((void**)&dinv, g_dinv);
    float* dinv_sim    = dinv;
    float* dinv_dist   = dinv + NN;
    float* dinv_common = dinv + 2 * NN;

    // ---- degree normalization for all three graphs ----
    fill_ones<<<(3 * NN + 255) / 256, 256>>>(dinv, 3 * NN);               // self-loop weight 1
    deg_accum<<<(EE + 255) / 256, 256>>>(sim_ei + EE,    sim_ew,    dinv_sim,    EE);
    deg_accum<<<(EE + 255) / 256, 256>>>(dist_ei + EE,   dist_ew,   dinv_dist,   EE);
    deg_accum<<<(EE + 255) / 256, 256>>>(common_ei + EE, common_ew, dinv_common, EE);
    rsqrt_inplace<<<(3 * NN + 255) / 256, 256>>>(dinv, 3 * NN);

    const int grid512 = (NN * (HIDDEN / 4) + 255) / 256;
    const int grid256 = (NN * (OUTD / 4) + 255) / 256;
    const int egrid512 = (EE + 1) / 2;   // 2 edges/block @ F=512, 256 threads
    const int egrid256 = (EE + 3) / 4;   // 4 edges/block @ F=256

    // ---- Layer 1, sim branch: xs = relu(gcn(x_RNA, sim; W_rna1, b_rna1)) ----
    gemm<false, false>(x_RNA, W_rna1, nullptr, h, NN, HIDDEN, INC);
    agg_init<<<grid512, 256>>>(h, dinv_sim, b_rna1, xs, HIDDEN);
    edge_agg<<<egrid512, 256>>>(h, xs, sim_ei, sim_ei + EE, sim_ew, dinv_sim, EE, HIDDEN);
    relu_inplace<<<(NN * HIDDEN + 255) / 256, 256>>>(xs, NN * HIDDEN);

    // ---- Layer 1, dist branch: xd = relu(gcn(x_RNA, dist; W_rna2, b_rna2)) ----
    gemm<false, false>(x_RNA, W_rna2, nullptr, h, NN, HIDDEN, INC);
    agg_init<<<grid512, 256>>>(h, dinv_dist, b_rna2, xd, HIDDEN);
    edge_agg<<<egrid512, 256>>>(h, xd, dist_ei, dist_ei + EE, dist_ew, dinv_dist, EE, HIDDEN);
    relu_inplace<<<(NN * HIDDEN + 255) / 256, 256>>>(xd, NN * HIDDEN);

    // ---- Layer 2: x_sim = gcn(xs, sim; W_sim, b_sim) -> d_out[0] ----
    gemm<false, false>(xs, W_sim, nullptr, h, NN, OUTD, HIDDEN);
    agg_init<<<grid256, 256>>>(h, dinv_sim, b_sim, out_xsim, OUTD);
    edge_agg<<<egrid256, 256>>>(h, out_xsim, sim_ei, sim_ei + EE, sim_ew, dinv_sim, EE, OUTD);

    // ---- Layer 2: x_dist = gcn(xd, dist; W_dist, b_dist) -> d_out[1] ----
    gemm<false, false>(xd, W_dist, nullptr, h, NN, OUTD, HIDDEN);
    agg_init<<<grid256, 256>>>(h, dinv_dist, b_dist, out_xdist, OUTD);
    edge_agg<<<egrid256, 256>>>(h, out_xdist, dist_ei, dist_ei + EE, dist_ew, dinv_dist, EE, OUTD);

    // ---- pro = gcn(x_ADT, common; W_p3, b_p3) -> d_out[4] ----
    gemm<false, false>(x_ADT, W_p3, nullptr, h, NN, OUTD, QD);
    agg_init<<<grid256, 256>>>(h, dinv_common, b_p3, out_pro, OUTD);
    edge_agg<<<egrid256, 256>>>(h, out_pro, common_ei, common_ei + EE, common_ew, dinv_common, EE, OUTD);

    // ---- fused = concat(x_sim, x_dist) @ W_f1 + b_f1  (K-split) -> d_out[2] ----
    gemm<false, true >(out_xsim,  W_f1,               b_f1,    out_fused, NN, OUTD, OUTD);
    gemm<true,  false>(out_xdist, W_f1 + OUTD * OUTD, nullptr, out_fused, NN, OUTD, OUTD);

    // ---- fused_pro = concat(fused, pro) @ W_f2 + b_f2 -> d_out[3] ----
    gemm<false, true >(out_fused, W_f2,               b_f2,    out_fpro, NN, OUTD, OUTD);
    gemm<true,  false>(out_pro,   W_f2 + OUTD * OUTD, nullptr, out_fpro, NN, OUTD, OUTD);
}